// round 13
// baseline (speedup 1.0000x reference)
#include <cuda_runtime.h>
#include <cuda_fp16.h>
#include <math.h>

#define NN 100000
#define NE 3200000
#define FULLMASK 0xffffffffu
#define GB1      ((NN + 255) / 256)   // 391 gemm blocks (layer1)
#define SB       2048                 // scatter blocks in fused kernel
#define CAP      96                   // slab capacity per dst (P(deg>96) ~ 1e-20)

// ---------------- scratch (device globals; no runtime allocation) ----------------
__device__ int2     g_se[(size_t)NN * CAP];  // slab-sorted (src, u-bits)
__device__ int      g_cur[NN];               // cursors; zero at load AND re-zeroed by agg2

// pair-interleaved tables: record p (8B) = { half2(y0[2p],y0[2p+1]), half2(y1[2p],y1[2p+1]) }
__device__ uint2   g_y01p[NN * 16];   // layer1: 16 pairs/node (32 feats)
__device__ float   g_r1 [NN * 32];
__device__ float   g_h  [NN * 32];

__device__ uint2   g_z01p[NN * 8];    // layer2: 8 pairs/node (16 feats)
__device__ float   g_r2 [NN * 16];

// ---------------- layer1 GEMM body: one node per thread (known-good R10) ------
__device__ __forceinline__ void gemm1_body(
    const float* __restrict__ xin,
    const float* __restrict__ W,      // [2,32,32]
    const float* __restrict__ root,   // [32,32]
    int base)
{
    constexpr int FO = 32;
    __shared__ __align__(16) float sW0[32 * FO];
    __shared__ __align__(16) float sW1[32 * FO];
    __shared__ __align__(16) float sR [32 * FO];
    int tid = threadIdx.x;

    for (int i = tid; i < 32 * FO; i += 256) {
        sW0[i] = W[i];
        sW1[i] = W[32 * FO + i];
        sR [i] = root[i];
    }

    int n = base + tid;
    float xr[32];
#pragma unroll
    for (int q = 0; q < 8; q++) {
        float4 v = make_float4(0.f, 0.f, 0.f, 0.f);
        if (n < NN) v = *reinterpret_cast<const float4*>(&xin[(size_t)n * 32 + q * 4]);
        xr[q*4+0] = v.x; xr[q*4+1] = v.y; xr[q*4+2] = v.z; xr[q*4+3] = v.w;
    }
    __syncthreads();

#pragma unroll
    for (int jg = 0; jg < FO / 4; jg++) {
        float4 ay0 = make_float4(0.f,0.f,0.f,0.f);
        float4 ay1 = ay0, ar = ay0;
#pragma unroll
        for (int k = 0; k < 32; k++) {
            float4 w0 = *reinterpret_cast<const float4*>(&sW0[k * FO + jg * 4]);
            float4 w1 = *reinterpret_cast<const float4*>(&sW1[k * FO + jg * 4]);
            float4 wr = *reinterpret_cast<const float4*>(&sR [k * FO + jg * 4]);
            float xk = xr[k];
            ay0.x += xk*w0.x; ay0.y += xk*w0.y; ay0.z += xk*w0.z; ay0.w += xk*w0.w;
            ay1.x += xk*w1.x; ay1.y += xk*w1.y; ay1.z += xk*w1.z; ay1.w += xk*w1.w;
            ar.x  += xk*wr.x; ar.y  += xk*wr.y; ar.z  += xk*wr.z; ar.w  += xk*wr.w;
        }
        if (n < NN) {
            __half2 h[4];
            h[0] = __floats2half2_rn(ay0.x, ay0.y);
            h[1] = __floats2half2_rn(ay1.x, ay1.y);
            h[2] = __floats2half2_rn(ay0.z, ay0.w);
            h[3] = __floats2half2_rn(ay1.z, ay1.w);
            *reinterpret_cast<float4*>(&g_y01p[n * (FO / 2) + jg * 2]) =
                *reinterpret_cast<float4*>(h);
            *reinterpret_cast<float4*>(&g_r1[(size_t)n * FO + jg * 4]) =
                make_float4(ar.x, ar.y, ar.z, ar.w);
        }
    }
}

// ---------------- fused: layer1 GEMM (blocks < GB1) + slab scatter ----------
__global__ __launch_bounds__(256) void gemm1_scatter(
    const float* __restrict__ x,
    const float* __restrict__ W,
    const float* __restrict__ root,
    const int*   __restrict__ ei32,
    const float* __restrict__ ea)
{
    if (blockIdx.x < GB1) {
        gemm1_body(x, W, root, blockIdx.x * 256);
        return;
    }

    // per-block int64-vs-int32 layout detection (64-thread vote)
    __shared__ int s_nz;
    if (threadIdx.x == 0) s_nz = 0;
    __syncthreads();
    if (threadIdx.x < 64 && ei32[2 * threadIdx.x + 1] != 0)
        atomicAdd(&s_nz, 1);
    __syncthreads();
    int is64 = (s_nz == 0);

    int b = blockIdx.x - GB1;
    // 2 edges per iteration -> two independent atomic/store chains in flight
    for (int e0 = b * 512 + threadIdx.x; e0 < NE; e0 += SB * 512) {
        int e1 = e0 + 256;
        int s0, d0, s1 = 0, d1 = 0;
        float u0, u1 = 0.f;
        bool has1 = (e1 < NE);
        if (is64) {
            s0 = ei32[2 * e0];
            d0 = ei32[2 * (NE + e0)];
            if (has1) { s1 = ei32[2 * e1]; d1 = ei32[2 * (NE + e1)]; }
        } else {
            s0 = ei32[e0];
            d0 = ei32[NE + e0];
            if (has1) { s1 = ei32[e1]; d1 = ei32[NE + e1]; }
        }
        u0 = fminf(fmaxf(ea[e0], 0.0f), 1.0f);
        if (has1) u1 = fminf(fmaxf(ea[e1], 0.0f), 1.0f);
        s0 = min(max(s0, 0), NN - 1);  d0 = min(max(d0, 0), NN - 1);
        int pos0 = atomicAdd(&g_cur[d0], 1);
        if (has1) {
            s1 = min(max(s1, 0), NN - 1);  d1 = min(max(d1, 0), NN - 1);
            int pos1 = atomicAdd(&g_cur[d1], 1);
            if (pos0 < CAP) g_se[(size_t)d0 * CAP + pos0] = make_int2(s0, __float_as_int(u0));
            if (pos1 < CAP) g_se[(size_t)d1 * CAP + pos1] = make_int2(s1, __float_as_int(u1));
        } else {
            if (pos0 < CAP) g_se[(size_t)d0 * CAP + pos0] = make_int2(s0, __float_as_int(u0));
        }
    }
}

// ---------------- layer2 GEMM: TWO threads per node ----------
__global__ __launch_bounds__(256) void gemm2_kernel(
    const float* __restrict__ W,      // [2,32,16]
    const float* __restrict__ root)   // [32,16]
{
    constexpr int FO = 16;
    __shared__ __align__(16) float sW0[32 * FO];
    __shared__ __align__(16) float sW1[32 * FO];
    __shared__ __align__(16) float sR [32 * FO];
    int tid = threadIdx.x;

    for (int i = tid; i < 32 * FO; i += 256) {
        sW0[i] = W[i];
        sW1[i] = W[32 * FO + i];
        sR [i] = root[i];
    }

    int n = blockIdx.x * 128 + (tid >> 1);
    int half = tid & 1;
    float xr[32];
#pragma unroll
    for (int q = 0; q < 8; q++) {
        float4 v = make_float4(0.f, 0.f, 0.f, 0.f);
        if (n < NN) v = *reinterpret_cast<const float4*>(&g_h[(size_t)n * 32 + q * 4]);
        xr[q*4+0] = v.x; xr[q*4+1] = v.y; xr[q*4+2] = v.z; xr[q*4+3] = v.w;
    }
    __syncthreads();

#pragma unroll
    for (int j = 0; j < 2; j++) {
        int jg = half * 2 + j;
        float4 ay0 = make_float4(0.f,0.f,0.f,0.f);
        float4 ay1 = ay0, ar = ay0;
#pragma unroll
        for (int k = 0; k < 32; k++) {
            float4 w0 = *reinterpret_cast<const float4*>(&sW0[k * FO + jg * 4]);
            float4 w1 = *reinterpret_cast<const float4*>(&sW1[k * FO + jg * 4]);
            float4 wr = *reinterpret_cast<const float4*>(&sR [k * FO + jg * 4]);
            float xk = xr[k];
            ay0.x += xk*w0.x; ay0.y += xk*w0.y; ay0.z += xk*w0.z; ay0.w += xk*w0.w;
            ay1.x += xk*w1.x; ay1.y += xk*w1.y; ay1.z += xk*w1.z; ay1.w += xk*w1.w;
            ar.x  += xk*wr.x; ar.y  += xk*wr.y; ar.z  += xk*wr.z; ar.w  += xk*wr.w;
        }
        if (n < NN) {
            __half2 h[4];
            h[0] = __floats2half2_rn(ay0.x, ay0.y);
            h[1] = __floats2half2_rn(ay1.x, ay1.y);
            h[2] = __floats2half2_rn(ay0.z, ay0.w);
            h[3] = __floats2half2_rn(ay1.z, ay1.w);
            *reinterpret_cast<float4*>(&g_z01p[n * 8 + jg * 2]) =
                *reinterpret_cast<float4*>(h);
            *reinterpret_cast<float4*>(&g_r2[(size_t)n * 16 + jg * 4]) =
                make_float4(ar.x, ar.y, ar.z, ar.w);
        }
    }
}

// lerp two packed features and accumulate
__device__ __forceinline__ void lerp2_acc(float2& acc, uint2 g, int ubits) {
    float2 f0 = __half22float2(*reinterpret_cast<__half2*>(&g.x));
    float2 f1 = __half22float2(*reinterpret_cast<__half2*>(&g.y));
    float u = __int_as_float(ubits);
    acc.x += fmaf(u, f1.x - f0.x, f0.x);
    acc.y += fmaf(u, f1.y - f0.y, f0.y);
}

// ---------------- layer1 aggregation: warp/node, int4 meta, 16-edge window ----
__global__ __launch_bounds__(256) void edge_agg1(const float* __restrict__ b1) {
    int tid = blockIdx.x * blockDim.x + threadIdx.x;
    int w = tid >> 5;
    int lane = threadIdx.x & 31;
    if (w >= NN) return;
    int cnt = min(g_cur[w], CAP);
    const int2* slab = g_se + (size_t)w * CAP;
    const int4* slab4 = reinterpret_cast<const int4*>(slab);
    int half = lane >> 4;        // edge-group parity
    int p    = lane & 15;        // feature pair

    float2 acc = make_float2(0.f, 0.f);
    int e = 0;
    // 16-edge window: each half loads 2 int4 (4 records) + 8 gathers in flight
    for (; e + 16 <= cnt; e += 16) {
        int base = e >> 1;
        int4 a = slab4[base + half];         // records e+2h .. e+2h+1
        int4 b = slab4[base + half + 2];     // records e+4+2h ..
        int4 c = slab4[base + half + 4];
        int4 d = slab4[base + half + 6];
        uint2 g0 = g_y01p[a.x * 16 + p];
        uint2 g1 = g_y01p[a.z * 16 + p];
        uint2 g2 = g_y01p[b.x * 16 + p];
        uint2 g3 = g_y01p[b.z * 16 + p];
        uint2 g4 = g_y01p[c.x * 16 + p];
        uint2 g5 = g_y01p[c.z * 16 + p];
        uint2 g6 = g_y01p[d.x * 16 + p];
        uint2 g7 = g_y01p[d.z * 16 + p];
        lerp2_acc(acc, g0, a.y); lerp2_acc(acc, g1, a.w);
        lerp2_acc(acc, g2, b.y); lerp2_acc(acc, g3, b.w);
        lerp2_acc(acc, g4, c.y); lerp2_acc(acc, g5, c.w);
        lerp2_acc(acc, g6, d.y); lerp2_acc(acc, g7, d.w);
    }
    // 8-edge window
    for (; e + 8 <= cnt; e += 8) {
        int base = e >> 1;
        int4 a = slab4[base + half];
        int4 b = slab4[base + half + 2];
        uint2 g0 = g_y01p[a.x * 16 + p];
        uint2 g1 = g_y01p[a.z * 16 + p];
        uint2 g2 = g_y01p[b.x * 16 + p];
        uint2 g3 = g_y01p[b.z * 16 + p];
        lerp2_acc(acc, g0, a.y); lerp2_acc(acc, g1, a.w);
        lerp2_acc(acc, g2, b.y); lerp2_acc(acc, g3, b.w);
    }
    // scalar tail (parity scheme)
    for (int t = e + half; t < cnt; t += 2) {
        int2 m = slab[t];
        lerp2_acc(acc, g_y01p[m.x * 16 + p], m.y);
    }
    acc.x += __shfl_xor_sync(FULLMASK, acc.x, 16);
    acc.y += __shfl_xor_sync(FULLMASK, acc.y, 16);

    float inv = 1.0f / fmaxf((float)cnt, 1.0f);
    float2 r = *reinterpret_cast<const float2*>(&g_r1[(size_t)w * 32 + 2 * p]);
    float2 b = *reinterpret_cast<const float2*>(&b1[2 * p]);
    float2 h;
    h.x = fmaxf(acc.x * inv + r.x + b.x, 0.0f);
    h.y = fmaxf(acc.y * inv + r.y + b.y, 0.0f);
    if (lane < 16)
        *reinterpret_cast<float2*>(&g_h[(size_t)w * 32 + 2 * p]) = h;
}

// ---------------- layer2 aggregation: warp/node, int4 meta, fused log_softmax --
__global__ __launch_bounds__(256) void edge_agg2(const float* __restrict__ b2,
                                                 float* __restrict__ out) {
    int tid = blockIdx.x * blockDim.x + threadIdx.x;
    int w = tid >> 5;
    int lane = threadIdx.x & 31;
    if (w >= NN) return;
    int cnt = min(g_cur[w], CAP);
    const int2* slab = g_se + (size_t)w * CAP;
    const int4* slab4 = reinterpret_cast<const int4*>(slab);
    int grp = lane >> 3;         // edge group (0..3)
    int p   = lane & 7;          // feature pair

    float2 acc = make_float2(0.f, 0.f);
    int e = 0;
    // 16-edge window: each group loads 2 int4 (4 records) + 4 gathers in flight
    for (; e + 16 <= cnt; e += 16) {
        int base = e >> 1;
        int4 a = slab4[base + grp];          // records e+2g, e+2g+1
        int4 b = slab4[base + grp + 4];      // records e+8+2g, ...
        uint2 g0 = g_z01p[a.x * 8 + p];
        uint2 g1 = g_z01p[a.z * 8 + p];
        uint2 g2 = g_z01p[b.x * 8 + p];
        uint2 g3 = g_z01p[b.z * 8 + p];
        lerp2_acc(acc, g0, a.y); lerp2_acc(acc, g1, a.w);
        lerp2_acc(acc, g2, b.y); lerp2_acc(acc, g3, b.w);
    }
    // 8-edge window
    for (; e + 8 <= cnt; e += 8) {
        int base = e >> 1;
        int4 a = slab4[base + grp];
        uint2 g0 = g_z01p[a.x * 8 + p];
        uint2 g1 = g_z01p[a.z * 8 + p];
        lerp2_acc(acc, g0, a.y); lerp2_acc(acc, g1, a.w);
    }
    // scalar tail
    for (int t = e + grp; t < cnt; t += 4) {
        int2 m = slab[t];
        lerp2_acc(acc, g_z01p[m.x * 8 + p], m.y);
    }
    // combine 4 edge groups
    acc.x += __shfl_xor_sync(FULLMASK, acc.x, 8);
    acc.y += __shfl_xor_sync(FULLMASK, acc.y, 8);
    acc.x += __shfl_xor_sync(FULLMASK, acc.x, 16);
    acc.y += __shfl_xor_sync(FULLMASK, acc.y, 16);

    float inv = 1.0f / fmaxf((float)cnt, 1.0f);
    float2 r = *reinterpret_cast<const float2*>(&g_r2[(size_t)w * 16 + 2 * p]);
    float2 b = *reinterpret_cast<const float2*>(&b2[2 * p]);
    float2 v;
    v.x = acc.x * inv + r.x + b.x;
    v.y = acc.y * inv + r.y + b.y;

    // log_softmax over 16 features
    float m = fmaxf(v.x, v.y);
#pragma unroll
    for (int off = 4; off >= 1; off >>= 1)
        m = fmaxf(m, __shfl_xor_sync(FULLMASK, m, off));
    float s = expf(v.x - m) + expf(v.y - m);
#pragma unroll
    for (int off = 4; off >= 1; off >>= 1)
        s += __shfl_xor_sync(FULLMASK, s, off);
    float lo = logf(s);
    if (lane < 8) {
        float2 o = make_float2(v.x - m - lo, v.y - m - lo);
        *reinterpret_cast<float2*>(&out[(size_t)w * 16 + 2 * p]) = o;
    }
    // reset cursor for the next graph replay (keeps kernel_launch deterministic)
    if (lane == 0) g_cur[w] = 0;
}

// ---------------- launch ----------------
extern "C" void kernel_launch(void* const* d_in, const int* in_sizes, int n_in,
                              void* d_out, int out_size) {
    const float* x   = (const float*)d_in[0];
    const int*   ei  = (const int*)d_in[1];
    const float* ea  = (const float*)d_in[2];
    const float* W1  = (const float*)d_in[3];
    const float* r1w = (const float*)d_in[4];
    const float* b1  = (const float*)d_in[5];
    const float* W2  = (const float*)d_in[6];
    const float* r2w = (const float*)d_in[7];
    const float* b2  = (const float*)d_in[8];
    float* out = (float*)d_out;

    gemm1_scatter<<<GB1 + SB, 256>>>(x, W1, r1w, ei, ea);
    edge_agg1<<<(NN * 32 + 255) / 256, 256>>>(b1);
    gemm2_kernel<<<(NN + 127) / 128, 256>>>(W2, r2w);
    edge_agg2<<<(NN * 32 + 255) / 256, 256>>>(b2, out);
}

// round 14
// speedup vs baseline: 1.4009x; 1.4009x over previous
#include <cuda_runtime.h>
#include <cuda_fp16.h>
#include <math.h>

#define NN 100000
#define NE 3200000
#define FULLMASK 0xffffffffu
#define GB1      ((NN + 255) / 256)   // 391 gemm blocks (layer1)
#define SB       2048                 // scatter blocks in fused kernel
#define CAP      96                   // slab capacity per dst (P(deg>96) ~ 1e-20)

// ---------------- scratch (device globals; no runtime allocation) ----------------
__device__ int2     g_se[(size_t)NN * CAP];  // slab-sorted (src, u-bits)
__device__ int      g_cur[NN];               // cursors; zero at load AND re-zeroed by agg2

// pair-interleaved tables: record p (8B) = { half2(y0[2p],y0[2p+1]), half2(y1[2p],y1[2p+1]) }
__device__ uint2   g_y01p[NN * 16];   // layer1: 16 pairs/node (32 feats)
__device__ float   g_r1 [NN * 32];
__device__ float   g_h  [NN * 32];

__device__ uint2   g_z01p[NN * 8];    // layer2: 8 pairs/node (16 feats)
__device__ float   g_r2 [NN * 16];

// ---------------- GEMM body: one node per thread, pair-interleaved pack out ----
template<int FO>
__device__ __forceinline__ void gemm_body(
    const float* __restrict__ xin,
    const float* __restrict__ W,      // [2,32,FO]
    const float* __restrict__ root,   // [32,FO]
    uint2*  __restrict__ packp,       // [NN * FO/2]
    float*  __restrict__ rout,        // [NN * FO]
    int base)
{
    __shared__ __align__(16) float sW0[32 * FO];
    __shared__ __align__(16) float sW1[32 * FO];
    __shared__ __align__(16) float sR [32 * FO];
    int tid = threadIdx.x;

    for (int i = tid; i < 32 * FO; i += 256) {
        sW0[i] = W[i];
        sW1[i] = W[32 * FO + i];
        sR [i] = root[i];
    }

    int n = base + tid;
    float xr[32];
#pragma unroll
    for (int q = 0; q < 8; q++) {
        float4 v = make_float4(0.f, 0.f, 0.f, 0.f);
        if (n < NN) v = *reinterpret_cast<const float4*>(&xin[(size_t)n * 32 + q * 4]);
        xr[q*4+0] = v.x; xr[q*4+1] = v.y; xr[q*4+2] = v.z; xr[q*4+3] = v.w;
    }
    __syncthreads();

#pragma unroll
    for (int jg = 0; jg < FO / 4; jg++) {
        float4 ay0 = make_float4(0.f,0.f,0.f,0.f);
        float4 ay1 = ay0, ar = ay0;
#pragma unroll
        for (int k = 0; k < 32; k++) {
            float4 w0 = *reinterpret_cast<const float4*>(&sW0[k * FO + jg * 4]);
            float4 w1 = *reinterpret_cast<const float4*>(&sW1[k * FO + jg * 4]);
            float4 wr = *reinterpret_cast<const float4*>(&sR [k * FO + jg * 4]);
            float xk = xr[k];
            ay0.x += xk*w0.x; ay0.y += xk*w0.y; ay0.z += xk*w0.z; ay0.w += xk*w0.w;
            ay1.x += xk*w1.x; ay1.y += xk*w1.y; ay1.z += xk*w1.z; ay1.w += xk*w1.w;
            ar.x  += xk*wr.x; ar.y  += xk*wr.y; ar.z  += xk*wr.z; ar.w  += xk*wr.w;
        }
        if (n < NN) {
            // pair 2jg = feats (4jg,4jg+1); pair 2jg+1 = feats (4jg+2,4jg+3)
            __half2 h[4];
            h[0] = __floats2half2_rn(ay0.x, ay0.y);   // y0 pair 2jg
            h[1] = __floats2half2_rn(ay1.x, ay1.y);   // y1 pair 2jg
            h[2] = __floats2half2_rn(ay0.z, ay0.w);   // y0 pair 2jg+1
            h[3] = __floats2half2_rn(ay1.z, ay1.w);   // y1 pair 2jg+1
            *reinterpret_cast<float4*>(&packp[n * (FO / 2) + jg * 2]) =
                *reinterpret_cast<float4*>(h);
            *reinterpret_cast<float4*>(&rout[(size_t)n * FO + jg * 4]) =
                make_float4(ar.x, ar.y, ar.z, ar.w);
        }
    }
}

// ---------------- fused: layer1 GEMM (blocks < GB1) + slab scatter ----------
__global__ __launch_bounds__(256) void gemm1_scatter(
    const float* __restrict__ x,
    const float* __restrict__ W,
    const float* __restrict__ root,
    const int*   __restrict__ ei32,
    const float* __restrict__ ea)
{
    if (blockIdx.x < GB1) {
        gemm_body<32>(x, W, root, g_y01p, g_r1, blockIdx.x * 256);
        return;
    }

    // per-block int64-vs-int32 layout detection (64-thread vote)
    __shared__ int s_nz;
    if (threadIdx.x == 0) s_nz = 0;
    __syncthreads();
    if (threadIdx.x < 64 && ei32[2 * threadIdx.x + 1] != 0)
        atomicAdd(&s_nz, 1);
    __syncthreads();
    int is64 = (s_nz == 0);

    int b = blockIdx.x - GB1;
    for (int e = b * 256 + threadIdx.x; e < NE; e += SB * 256) {
        int s, d;
        if (is64) {
            s = ei32[2 * e];
            d = ei32[2 * (NE + e)];
        } else {
            s = ei32[e];
            d = ei32[NE + e];
        }
        s = min(max(s, 0), NN - 1);
        d = min(max(d, 0), NN - 1);
        float u = fminf(fmaxf(ea[e], 0.0f), 1.0f);
        int pos = atomicAdd(&g_cur[d], 1);
        if (pos < CAP) g_se[(size_t)d * CAP + pos] = make_int2(s, __float_as_int(u));
    }
}

// ---------------- layer2 GEMM ----------------
__global__ __launch_bounds__(256) void gemm2_kernel(
    const float* __restrict__ W,
    const float* __restrict__ root)
{
    gemm_body<16>(g_h, W, root, g_z01p, g_r2, blockIdx.x * 256);
}

// lerp two packed features and accumulate
__device__ __forceinline__ void lerp2_acc(float2& acc, uint2 g, int ubits) {
    float2 f0 = __half22float2(*reinterpret_cast<__half2*>(&g.x));
    float2 f1 = __half22float2(*reinterpret_cast<__half2*>(&g.y));
    float u = __int_as_float(ubits);
    acc.x += fmaf(u, f1.x - f0.x, f0.x);
    acc.y += fmaf(u, f1.y - f0.y, f0.y);
}

// ---------------- layer1 aggregation: warp/node, 16 lanes x 2 feats, 2 edges ---
__global__ __launch_bounds__(256) void edge_agg1(const float* __restrict__ b1) {
    int tid = blockIdx.x * blockDim.x + threadIdx.x;
    int w = tid >> 5;
    int lane = threadIdx.x & 31;
    if (w >= NN) return;
    int cnt = min(g_cur[w], CAP);
    const int2* slab = g_se + (size_t)w * CAP;
    int half = lane >> 4;        // edge parity
    int p    = lane & 15;        // feature pair

    float2 acc = make_float2(0.f, 0.f);
    int e = half;
    // 16-edge window: 8 gathers in flight per lane
    for (; e + 14 < cnt; e += 16) {
        int2 m0 = slab[e],    m1 = slab[e+2],  m2 = slab[e+4],  m3 = slab[e+6];
        int2 m4 = slab[e+8],  m5 = slab[e+10], m6 = slab[e+12], m7 = slab[e+14];
        uint2 g0 = g_y01p[m0.x * 16 + p];
        uint2 g1 = g_y01p[m1.x * 16 + p];
        uint2 g2 = g_y01p[m2.x * 16 + p];
        uint2 g3 = g_y01p[m3.x * 16 + p];
        uint2 g4 = g_y01p[m4.x * 16 + p];
        uint2 g5 = g_y01p[m5.x * 16 + p];
        uint2 g6 = g_y01p[m6.x * 16 + p];
        uint2 g7 = g_y01p[m7.x * 16 + p];
        lerp2_acc(acc, g0, m0.y); lerp2_acc(acc, g1, m1.y);
        lerp2_acc(acc, g2, m2.y); lerp2_acc(acc, g3, m3.y);
        lerp2_acc(acc, g4, m4.y); lerp2_acc(acc, g5, m5.y);
        lerp2_acc(acc, g6, m6.y); lerp2_acc(acc, g7, m7.y);
    }
    // 8-edge window
    for (; e + 6 < cnt; e += 8) {
        int2 m0 = slab[e], m1 = slab[e+2], m2 = slab[e+4], m3 = slab[e+6];
        uint2 g0 = g_y01p[m0.x * 16 + p];
        uint2 g1 = g_y01p[m1.x * 16 + p];
        uint2 g2 = g_y01p[m2.x * 16 + p];
        uint2 g3 = g_y01p[m3.x * 16 + p];
        lerp2_acc(acc, g0, m0.y); lerp2_acc(acc, g1, m1.y);
        lerp2_acc(acc, g2, m2.y); lerp2_acc(acc, g3, m3.y);
    }
    for (; e < cnt; e += 2) {
        int2 m = slab[e];
        lerp2_acc(acc, g_y01p[m.x * 16 + p], m.y);
    }
    acc.x += __shfl_xor_sync(FULLMASK, acc.x, 16);
    acc.y += __shfl_xor_sync(FULLMASK, acc.y, 16);

    float inv = 1.0f / fmaxf((float)cnt, 1.0f);
    float2 r = *reinterpret_cast<const float2*>(&g_r1[(size_t)w * 32 + 2 * p]);
    float2 b = *reinterpret_cast<const float2*>(&b1[2 * p]);
    float2 h;
    h.x = fmaxf(acc.x * inv + r.x + b.x, 0.0f);
    h.y = fmaxf(acc.y * inv + r.y + b.y, 0.0f);
    if (lane < 16)
        *reinterpret_cast<float2*>(&g_h[(size_t)w * 32 + 2 * p]) = h;
}

// ---------------- layer2 aggregation: warp/node, 8 lanes x 2 feats, 4 edges ----
// fused log_softmax epilogue; resets cursor for next replay
__global__ __launch_bounds__(256) void edge_agg2(const float* __restrict__ b2,
                                                 float* __restrict__ out) {
    int tid = blockIdx.x * blockDim.x + threadIdx.x;
    int w = tid >> 5;
    int lane = threadIdx.x & 31;
    if (w >= NN) return;
    int cnt = min(g_cur[w], CAP);
    const int2* slab = g_se + (size_t)w * CAP;
    int grp = lane >> 3;         // edge slot mod 4
    int p   = lane & 7;          // feature pair

    float2 acc = make_float2(0.f, 0.f);
    int e = grp;
    // 16-edge window: 4 gathers in flight per lane
    for (; e + 12 < cnt; e += 16) {
        int2 m0 = slab[e], m1 = slab[e+4], m2 = slab[e+8], m3 = slab[e+12];
        uint2 g0 = g_z01p[m0.x * 8 + p];
        uint2 g1 = g_z01p[m1.x * 8 + p];
        uint2 g2 = g_z01p[m2.x * 8 + p];
        uint2 g3 = g_z01p[m3.x * 8 + p];
        lerp2_acc(acc, g0, m0.y); lerp2_acc(acc, g1, m1.y);
        lerp2_acc(acc, g2, m2.y); lerp2_acc(acc, g3, m3.y);
    }
    for (; e < cnt; e += 4) {
        int2 m = slab[e];
        lerp2_acc(acc, g_z01p[m.x * 8 + p], m.y);
    }
    // combine 4 edge groups
    acc.x += __shfl_xor_sync(FULLMASK, acc.x, 8);
    acc.y += __shfl_xor_sync(FULLMASK, acc.y, 8);
    acc.x += __shfl_xor_sync(FULLMASK, acc.x, 16);
    acc.y += __shfl_xor_sync(FULLMASK, acc.y, 16);

    float inv = 1.0f / fmaxf((float)cnt, 1.0f);
    float2 r = *reinterpret_cast<const float2*>(&g_r2[(size_t)w * 16 + 2 * p]);
    float2 b = *reinterpret_cast<const float2*>(&b2[2 * p]);
    float2 v;
    v.x = acc.x * inv + r.x + b.x;
    v.y = acc.y * inv + r.y + b.y;

    // log_softmax over 16 features (replicated across the 4 groups)
    float m = fmaxf(v.x, v.y);
#pragma unroll
    for (int off = 4; off >= 1; off >>= 1)
        m = fmaxf(m, __shfl_xor_sync(FULLMASK, m, off));
    float s = expf(v.x - m) + expf(v.y - m);
#pragma unroll
    for (int off = 4; off >= 1; off >>= 1)
        s += __shfl_xor_sync(FULLMASK, s, off);
    float lo = logf(s);
    if (lane < 8) {
        float2 o = make_float2(v.x - m - lo, v.y - m - lo);
        *reinterpret_cast<float2*>(&out[(size_t)w * 16 + 2 * p]) = o;
    }
    // reset cursor for the next graph replay (keeps kernel_launch deterministic)
    if (lane == 0) g_cur[w] = 0;
}

// ---------------- launch ----------------
extern "C" void kernel_launch(void* const* d_in, const int* in_sizes, int n_in,
                              void* d_out, int out_size) {
    const float* x   = (const float*)d_in[0];
    const int*   ei  = (const int*)d_in[1];
    const float* ea  = (const float*)d_in[2];
    const float* W1  = (const float*)d_in[3];
    const float* r1w = (const float*)d_in[4];
    const float* b1  = (const float*)d_in[5];
    const float* W2  = (const float*)d_in[6];
    const float* r2w = (const float*)d_in[7];
    const float* b2  = (const float*)d_in[8];
    float* out = (float*)d_out;

    gemm1_scatter<<<GB1 + SB, 256>>>(x, W1, r1w, ei, ea);
    edge_agg1<<<(NN * 32 + 255) / 256, 256>>>(b1);
    gemm2_kernel<<<(NN + 255) / 256, 256>>>(W2, r2w);
    edge_agg2<<<(NN * 32 + 255) / 256, 256>>>(b2, out);
}

// round 15
// speedup vs baseline: 1.4069x; 1.0043x over previous
#include <cuda_runtime.h>
#include <cuda_fp16.h>
#include <math.h>

#define NN 100000
#define NE 3200000
#define FULLMASK 0xffffffffu
#define GB1      ((NN + 255) / 256)   // 391 gemm blocks (layer1)
#define SB       2048                 // scatter blocks in fused kernel
#define CAP      96                   // slab capacity per dst (P(deg>96) ~ 1e-20)

// ---------------- scratch (device globals; no runtime allocation) ----------------
// meta record: (src, u as broadcast half2)
__device__ int2     g_se[(size_t)NN * CAP];  // slab-sorted (src, uh2-bits)
__device__ int      g_cur[NN];               // cursors; zero at load AND re-zeroed by agg2

// pair-interleaved tables: record p (8B) = { half2(y0[2p],y0[2p+1]), half2(y1[2p],y1[2p+1]) }
__device__ uint2   g_y01p[NN * 16];   // layer1: 16 pairs/node (32 feats)
__device__ float   g_r1 [NN * 32];
__device__ float   g_h  [NN * 32];

__device__ uint2   g_z01p[NN * 8];    // layer2: 8 pairs/node (16 feats)
__device__ float   g_r2 [NN * 16];

// ---------------- GEMM body: one node per thread, pair-interleaved pack out ----
template<int FO>
__device__ __forceinline__ void gemm_body(
    const float* __restrict__ xin,
    const float* __restrict__ W,      // [2,32,FO]
    const float* __restrict__ root,   // [32,FO]
    uint2*  __restrict__ packp,       // [NN * FO/2]
    float*  __restrict__ rout,        // [NN * FO]
    int base)
{
    __shared__ __align__(16) float sW0[32 * FO];
    __shared__ __align__(16) float sW1[32 * FO];
    __shared__ __align__(16) float sR [32 * FO];
    int tid = threadIdx.x;

    for (int i = tid; i < 32 * FO; i += 256) {
        sW0[i] = W[i];
        sW1[i] = W[32 * FO + i];
        sR [i] = root[i];
    }

    int n = base + tid;
    float xr[32];
#pragma unroll
    for (int q = 0; q < 8; q++) {
        float4 v = make_float4(0.f, 0.f, 0.f, 0.f);
        if (n < NN) v = *reinterpret_cast<const float4*>(&xin[(size_t)n * 32 + q * 4]);
        xr[q*4+0] = v.x; xr[q*4+1] = v.y; xr[q*4+2] = v.z; xr[q*4+3] = v.w;
    }
    __syncthreads();

#pragma unroll
    for (int jg = 0; jg < FO / 4; jg++) {
        float4 ay0 = make_float4(0.f,0.f,0.f,0.f);
        float4 ay1 = ay0, ar = ay0;
#pragma unroll
        for (int k = 0; k < 32; k++) {
            float4 w0 = *reinterpret_cast<const float4*>(&sW0[k * FO + jg * 4]);
            float4 w1 = *reinterpret_cast<const float4*>(&sW1[k * FO + jg * 4]);
            float4 wr = *reinterpret_cast<const float4*>(&sR [k * FO + jg * 4]);
            float xk = xr[k];
            ay0.x += xk*w0.x; ay0.y += xk*w0.y; ay0.z += xk*w0.z; ay0.w += xk*w0.w;
            ay1.x += xk*w1.x; ay1.y += xk*w1.y; ay1.z += xk*w1.z; ay1.w += xk*w1.w;
            ar.x  += xk*wr.x; ar.y  += xk*wr.y; ar.z  += xk*wr.z; ar.w  += xk*wr.w;
        }
        if (n < NN) {
            // pair 2jg = feats (4jg,4jg+1); pair 2jg+1 = feats (4jg+2,4jg+3)
            __half2 h[4];
            h[0] = __floats2half2_rn(ay0.x, ay0.y);   // y0 pair 2jg
            h[1] = __floats2half2_rn(ay1.x, ay1.y);   // y1 pair 2jg
            h[2] = __floats2half2_rn(ay0.z, ay0.w);   // y0 pair 2jg+1
            h[3] = __floats2half2_rn(ay1.z, ay1.w);   // y1 pair 2jg+1
            *reinterpret_cast<float4*>(&packp[n * (FO / 2) + jg * 2]) =
                *reinterpret_cast<float4*>(h);
            *reinterpret_cast<float4*>(&rout[(size_t)n * FO + jg * 4]) =
                make_float4(ar.x, ar.y, ar.z, ar.w);
        }
    }
}

// ---------------- fused: layer1 GEMM (blocks < GB1) + slab scatter ----------
__global__ __launch_bounds__(256) void gemm1_scatter(
    const float* __restrict__ x,
    const float* __restrict__ W,
    const float* __restrict__ root,
    const int*   __restrict__ ei32,
    const float* __restrict__ ea)
{
    if (blockIdx.x < GB1) {
        gemm_body<32>(x, W, root, g_y01p, g_r1, blockIdx.x * 256);
        return;
    }

    // per-block int64-vs-int32 layout detection (64-thread vote)
    __shared__ int s_nz;
    if (threadIdx.x == 0) s_nz = 0;
    __syncthreads();
    if (threadIdx.x < 64 && ei32[2 * threadIdx.x + 1] != 0)
        atomicAdd(&s_nz, 1);
    __syncthreads();
    int is64 = (s_nz == 0);

    int b = blockIdx.x - GB1;
    for (int e = b * 256 + threadIdx.x; e < NE; e += SB * 256) {
        int s, d;
        if (is64) {
            s = ei32[2 * e];
            d = ei32[2 * (NE + e)];
        } else {
            s = ei32[e];
            d = ei32[NE + e];
        }
        s = min(max(s, 0), NN - 1);
        d = min(max(d, 0), NN - 1);
        float u = fminf(fmaxf(ea[e], 0.0f), 1.0f);
        __half2 uh2 = __float2half2_rn(u);          // broadcast u once at scatter time
        int pos = atomicAdd(&g_cur[d], 1);
        if (pos < CAP)
            g_se[(size_t)d * CAP + pos] =
                make_int2(s, (int)*reinterpret_cast<unsigned*>(&uh2));
    }
}

// ---------------- layer2 GEMM ----------------
__global__ __launch_bounds__(256) void gemm2_kernel(
    const float* __restrict__ W,
    const float* __restrict__ root)
{
    gemm_body<16>(g_h, W, root, g_z01p, g_r2, blockIdx.x * 256);
}

// fp16 lerp (HSUB2+HFMA2), fp32 accumulate: 6 issue slots vs 10 for fp32 lerp
__device__ __forceinline__ void lerp2_acc(float2& acc, uint2 g, int uh2bits) {
    __half2 h0 = *reinterpret_cast<__half2*>(&g.x);
    __half2 h1 = *reinterpret_cast<__half2*>(&g.y);
    __half2 u2 = *reinterpret_cast<__half2*>(&uh2bits);
    __half2 m  = __hfma2(u2, __hsub2(h1, h0), h0);
    float2 mf = __half22float2(m);
    acc.x += mf.x;
    acc.y += mf.y;
}

// ---------------- layer1 aggregation: warp/node, 16 lanes x 2 feats, 2 edges ---
__global__ __launch_bounds__(256) void edge_agg1(const float* __restrict__ b1) {
    int tid = blockIdx.x * blockDim.x + threadIdx.x;
    int w = tid >> 5;
    int lane = threadIdx.x & 31;
    if (w >= NN) return;
    int cnt = min(g_cur[w], CAP);
    const int2* slab = g_se + (size_t)w * CAP;
    int half = lane >> 4;        // edge parity
    int p    = lane & 15;        // feature pair

    float2 acc = make_float2(0.f, 0.f);
    int e = half;
    // 16-edge window: 8 gathers in flight per lane
    for (; e + 14 < cnt; e += 16) {
        int2 m0 = slab[e],    m1 = slab[e+2],  m2 = slab[e+4],  m3 = slab[e+6];
        int2 m4 = slab[e+8],  m5 = slab[e+10], m6 = slab[e+12], m7 = slab[e+14];
        uint2 g0 = g_y01p[m0.x * 16 + p];
        uint2 g1 = g_y01p[m1.x * 16 + p];
        uint2 g2 = g_y01p[m2.x * 16 + p];
        uint2 g3 = g_y01p[m3.x * 16 + p];
        uint2 g4 = g_y01p[m4.x * 16 + p];
        uint2 g5 = g_y01p[m5.x * 16 + p];
        uint2 g6 = g_y01p[m6.x * 16 + p];
        uint2 g7 = g_y01p[m7.x * 16 + p];
        lerp2_acc(acc, g0, m0.y); lerp2_acc(acc, g1, m1.y);
        lerp2_acc(acc, g2, m2.y); lerp2_acc(acc, g3, m3.y);
        lerp2_acc(acc, g4, m4.y); lerp2_acc(acc, g5, m5.y);
        lerp2_acc(acc, g6, m6.y); lerp2_acc(acc, g7, m7.y);
    }
    // 8-edge window
    for (; e + 6 < cnt; e += 8) {
        int2 m0 = slab[e], m1 = slab[e+2], m2 = slab[e+4], m3 = slab[e+6];
        uint2 g0 = g_y01p[m0.x * 16 + p];
        uint2 g1 = g_y01p[m1.x * 16 + p];
        uint2 g2 = g_y01p[m2.x * 16 + p];
        uint2 g3 = g_y01p[m3.x * 16 + p];
        lerp2_acc(acc, g0, m0.y); lerp2_acc(acc, g1, m1.y);
        lerp2_acc(acc, g2, m2.y); lerp2_acc(acc, g3, m3.y);
    }
    for (; e < cnt; e += 2) {
        int2 m = slab[e];
        lerp2_acc(acc, g_y01p[m.x * 16 + p], m.y);
    }
    acc.x += __shfl_xor_sync(FULLMASK, acc.x, 16);
    acc.y += __shfl_xor_sync(FULLMASK, acc.y, 16);

    float inv = 1.0f / fmaxf((float)cnt, 1.0f);
    float2 r = *reinterpret_cast<const float2*>(&g_r1[(size_t)w * 32 + 2 * p]);
    float2 b = *reinterpret_cast<const float2*>(&b1[2 * p]);
    float2 h;
    h.x = fmaxf(acc.x * inv + r.x + b.x, 0.0f);
    h.y = fmaxf(acc.y * inv + r.y + b.y, 0.0f);
    if (lane < 16)
        *reinterpret_cast<float2*>(&g_h[(size_t)w * 32 + 2 * p]) = h;
}

// ---------------- layer2 aggregation: warp/node, 8 lanes x 2 feats, 4 edges ----
// fused log_softmax epilogue; resets cursor for next replay
__global__ __launch_bounds__(256) void edge_agg2(const float* __restrict__ b2,
                                                 float* __restrict__ out) {
    int tid = blockIdx.x * blockDim.x + threadIdx.x;
    int w = tid >> 5;
    int lane = threadIdx.x & 31;
    if (w >= NN) return;
    int cnt = min(g_cur[w], CAP);
    const int2* slab = g_se + (size_t)w * CAP;
    int grp = lane >> 3;         // edge slot mod 4
    int p   = lane & 7;          // feature pair

    float2 acc = make_float2(0.f, 0.f);
    int e = grp;
    // 16-edge window: 4 gathers in flight per lane
    for (; e + 12 < cnt; e += 16) {
        int2 m0 = slab[e], m1 = slab[e+4], m2 = slab[e+8], m3 = slab[e+12];
        uint2 g0 = g_z01p[m0.x * 8 + p];
        uint2 g1 = g_z01p[m1.x * 8 + p];
        uint2 g2 = g_z01p[m2.x * 8 + p];
        uint2 g3 = g_z01p[m3.x * 8 + p];
        lerp2_acc(acc, g0, m0.y); lerp2_acc(acc, g1, m1.y);
        lerp2_acc(acc, g2, m2.y); lerp2_acc(acc, g3, m3.y);
    }
    for (; e < cnt; e += 4) {
        int2 m = slab[e];
        lerp2_acc(acc, g_z01p[m.x * 8 + p], m.y);
    }
    // combine 4 edge groups
    acc.x += __shfl_xor_sync(FULLMASK, acc.x, 8);
    acc.y += __shfl_xor_sync(FULLMASK, acc.y, 8);
    acc.x += __shfl_xor_sync(FULLMASK, acc.x, 16);
    acc.y += __shfl_xor_sync(FULLMASK, acc.y, 16);

    float inv = 1.0f / fmaxf((float)cnt, 1.0f);
    float2 r = *reinterpret_cast<const float2*>(&g_r2[(size_t)w * 16 + 2 * p]);
    float2 b = *reinterpret_cast<const float2*>(&b2[2 * p]);
    float2 v;
    v.x = acc.x * inv + r.x + b.x;
    v.y = acc.y * inv + r.y + b.y;

    // log_softmax over 16 features (replicated across the 4 groups)
    float m = fmaxf(v.x, v.y);
#pragma unroll
    for (int off = 4; off >= 1; off >>= 1)
        m = fmaxf(m, __shfl_xor_sync(FULLMASK, m, off));
    float s = expf(v.x - m) + expf(v.y - m);
#pragma unroll
    for (int off = 4; off >= 1; off >>= 1)
        s += __shfl_xor_sync(FULLMASK, s, off);
    float lo = logf(s);
    if (lane < 8) {
        float2 o = make_float2(v.x - m - lo, v.y - m - lo);
        *reinterpret_cast<float2*>(&out[(size_t)w * 16 + 2 * p]) = o;
    }
    // reset cursor for the next graph replay (keeps kernel_launch deterministic)
    if (lane == 0) g_cur[w] = 0;
}

// ---------------- launch ----------------
extern "C" void kernel_launch(void* const* d_in, const int* in_sizes, int n_in,
                              void* d_out, int out_size) {
    const float* x   = (const float*)d_in[0];
    const int*   ei  = (const int*)d_in[1];
    const float* ea  = (const float*)d_in[2];
    const float* W1  = (const float*)d_in[3];
    const float* r1w = (const float*)d_in[4];
    const float* b1  = (const float*)d_in[5];
    const float* W2  = (const float*)d_in[6];
    const float* r2w = (const float*)d_in[7];
    const float* b2  = (const float*)d_in[8];
    float* out = (float*)d_out;

    gemm1_scatter<<<GB1 + SB, 256>>>(x, W1, r1w, ei, ea);
    edge_agg1<<<(NN * 32 + 255) / 256, 256>>>(b1);
    gemm2_kernel<<<(NN + 255) / 256, 256>>>(W2, r2w);
    edge_agg2<<<(NN * 32 + 255) / 256, 256>>>(b2, out);
}

// round 16
// speedup vs baseline: 1.4398x; 1.0234x over previous
#include <cuda_runtime.h>
#include <cuda_fp16.h>
#include <math.h>

#define NN 100000
#define NE 3200000
#define FULLMASK 0xffffffffu
#define GB1      ((NN + 255) / 256)   // 391 gemm blocks (layer1)
#define SB       2048                 // scatter blocks in fused kernel
#define CAP      96                   // slab capacity per dst (P(deg>96) ~ 1e-20)

// ---------------- scratch (device globals; no runtime allocation) ----------------
// meta record: (src, u as broadcast half2)
__device__ int2     g_se[(size_t)NN * CAP];  // slab-sorted (src, uh2-bits)
__device__ int      g_cur[NN];               // cursors; zero at load AND re-zeroed by agg2

// pair-interleaved tables: record p (8B) = { half2(y0[2p],y0[2p+1]), half2(y1[2p],y1[2p+1]) }
__device__ uint2   g_y01p[NN * 16];   // layer1: 16 pairs/node (32 feats)
__device__ float   g_r1 [NN * 32];
__device__ float   g_h  [NN * 32];

__device__ uint2   g_z01p[NN * 8];    // layer2: 8 pairs/node (16 feats)
__device__ float   g_r2 [NN * 16];

// ---------------- GEMM body: one node per thread, pair-interleaved pack out ----
template<int FO>
__device__ __forceinline__ void gemm_body(
    const float* __restrict__ xin,
    const float* __restrict__ W,      // [2,32,FO]
    const float* __restrict__ root,   // [32,FO]
    uint2*  __restrict__ packp,       // [NN * FO/2]
    float*  __restrict__ rout,        // [NN * FO]
    int base)
{
    __shared__ __align__(16) float sW0[32 * FO];
    __shared__ __align__(16) float sW1[32 * FO];
    __shared__ __align__(16) float sR [32 * FO];
    int tid = threadIdx.x;

    for (int i = tid; i < 32 * FO; i += 256) {
        sW0[i] = W[i];
        sW1[i] = W[32 * FO + i];
        sR [i] = root[i];
    }

    int n = base + tid;
    float xr[32];
#pragma unroll
    for (int q = 0; q < 8; q++) {
        float4 v = make_float4(0.f, 0.f, 0.f, 0.f);
        if (n < NN) v = *reinterpret_cast<const float4*>(&xin[(size_t)n * 32 + q * 4]);
        xr[q*4+0] = v.x; xr[q*4+1] = v.y; xr[q*4+2] = v.z; xr[q*4+3] = v.w;
    }
    __syncthreads();

#pragma unroll
    for (int jg = 0; jg < FO / 4; jg++) {
        float4 ay0 = make_float4(0.f,0.f,0.f,0.f);
        float4 ay1 = ay0, ar = ay0;
#pragma unroll
        for (int k = 0; k < 32; k++) {
            float4 w0 = *reinterpret_cast<const float4*>(&sW0[k * FO + jg * 4]);
            float4 w1 = *reinterpret_cast<const float4*>(&sW1[k * FO + jg * 4]);
            float4 wr = *reinterpret_cast<const float4*>(&sR [k * FO + jg * 4]);
            float xk = xr[k];
            ay0.x += xk*w0.x; ay0.y += xk*w0.y; ay0.z += xk*w0.z; ay0.w += xk*w0.w;
            ay1.x += xk*w1.x; ay1.y += xk*w1.y; ay1.z += xk*w1.z; ay1.w += xk*w1.w;
            ar.x  += xk*wr.x; ar.y  += xk*wr.y; ar.z  += xk*wr.z; ar.w  += xk*wr.w;
        }
        if (n < NN) {
            // pair 2jg = feats (4jg,4jg+1); pair 2jg+1 = feats (4jg+2,4jg+3)
            __half2 h[4];
            h[0] = __floats2half2_rn(ay0.x, ay0.y);   // y0 pair 2jg
            h[1] = __floats2half2_rn(ay1.x, ay1.y);   // y1 pair 2jg
            h[2] = __floats2half2_rn(ay0.z, ay0.w);   // y0 pair 2jg+1
            h[3] = __floats2half2_rn(ay1.z, ay1.w);   // y1 pair 2jg+1
            *reinterpret_cast<float4*>(&packp[n * (FO / 2) + jg * 2]) =
                *reinterpret_cast<float4*>(h);
            *reinterpret_cast<float4*>(&rout[(size_t)n * FO + jg * 4]) =
                make_float4(ar.x, ar.y, ar.z, ar.w);
        }
    }
}

// ---------------- fused: layer1 GEMM (blocks < GB1) + slab scatter ----------
__global__ __launch_bounds__(256) void gemm1_scatter(
    const float* __restrict__ x,
    const float* __restrict__ W,
    const float* __restrict__ root,
    const int*   __restrict__ ei32,
    const float* __restrict__ ea)
{
    if (blockIdx.x < GB1) {
        gemm_body<32>(x, W, root, g_y01p, g_r1, blockIdx.x * 256);
        return;
    }

    // per-block int64-vs-int32 layout detection (64-thread vote)
    __shared__ int s_nz;
    if (threadIdx.x == 0) s_nz = 0;
    __syncthreads();
    if (threadIdx.x < 64 && ei32[2 * threadIdx.x + 1] != 0)
        atomicAdd(&s_nz, 1);
    __syncthreads();
    int is64 = (s_nz == 0);

    int b = blockIdx.x - GB1;
    for (int e = b * 256 + threadIdx.x; e < NE; e += SB * 256) {
        int s, d;
        if (is64) {
            s = ei32[2 * e];
            d = ei32[2 * (NE + e)];
        } else {
            s = ei32[e];
            d = ei32[NE + e];
        }
        s = min(max(s, 0), NN - 1);
        d = min(max(d, 0), NN - 1);
        float u = fminf(fmaxf(ea[e], 0.0f), 1.0f);
        __half2 uh2 = __float2half2_rn(u);          // broadcast u once at scatter time
        int pos = atomicAdd(&g_cur[d], 1);
        if (pos < CAP)
            g_se[(size_t)d * CAP + pos] =
                make_int2(s, (int)*reinterpret_cast<unsigned*>(&uh2));
    }
}

// ---------------- layer2 GEMM ----------------
__global__ __launch_bounds__(256) void gemm2_kernel(
    const float* __restrict__ W,
    const float* __restrict__ root)
{
    gemm_body<16>(g_h, W, root, g_z01p, g_r2, blockIdx.x * 256);
}

// fp16 lerp (HSUB2+HFMA2), fp32 accumulate — used in agg1 (measured win there)
__device__ __forceinline__ void lerp2_acc_h(float2& acc, uint2 g, int uh2bits) {
    __half2 h0 = *reinterpret_cast<__half2*>(&g.x);
    __half2 h1 = *reinterpret_cast<__half2*>(&g.y);
    __half2 u2 = *reinterpret_cast<__half2*>(&uh2bits);
    __half2 m  = __hfma2(u2, __hsub2(h1, h0), h0);
    float2 mf = __half22float2(m);
    acc.x += mf.x;
    acc.y += mf.y;
}

// fp32 lerp — used in agg2 (measured faster there; lower reg pressure)
__device__ __forceinline__ void lerp2_acc_f(float2& acc, uint2 g, int uh2bits) {
    float2 f0 = __half22float2(*reinterpret_cast<__half2*>(&g.x));
    float2 f1 = __half22float2(*reinterpret_cast<__half2*>(&g.y));
    float u = __low2float(*reinterpret_cast<__half2*>(&uh2bits));
    acc.x += fmaf(u, f1.x - f0.x, f0.x);
    acc.y += fmaf(u, f1.y - f0.y, f0.y);
}

// ---------------- layer1 aggregation: warp/node, 16 lanes x 2 feats, 2 edges ---
__global__ __launch_bounds__(256) void edge_agg1(const float* __restrict__ b1) {
    int tid = blockIdx.x * blockDim.x + threadIdx.x;
    int w = tid >> 5;
    int lane = threadIdx.x & 31;
    if (w >= NN) return;
    int cnt = min(g_cur[w], CAP);
    const int2* slab = g_se + (size_t)w * CAP;
    int half = lane >> 4;        // edge parity
    int p    = lane & 15;        // feature pair

    float2 acc = make_float2(0.f, 0.f);
    int e = half;
    // 16-edge window: 8 gathers in flight per lane
    for (; e + 14 < cnt; e += 16) {
        int2 m0 = slab[e],    m1 = slab[e+2],  m2 = slab[e+4],  m3 = slab[e+6];
        int2 m4 = slab[e+8],  m5 = slab[e+10], m6 = slab[e+12], m7 = slab[e+14];
        uint2 g0 = g_y01p[m0.x * 16 + p];
        uint2 g1 = g_y01p[m1.x * 16 + p];
        uint2 g2 = g_y01p[m2.x * 16 + p];
        uint2 g3 = g_y01p[m3.x * 16 + p];
        uint2 g4 = g_y01p[m4.x * 16 + p];
        uint2 g5 = g_y01p[m5.x * 16 + p];
        uint2 g6 = g_y01p[m6.x * 16 + p];
        uint2 g7 = g_y01p[m7.x * 16 + p];
        lerp2_acc_h(acc, g0, m0.y); lerp2_acc_h(acc, g1, m1.y);
        lerp2_acc_h(acc, g2, m2.y); lerp2_acc_h(acc, g3, m3.y);
        lerp2_acc_h(acc, g4, m4.y); lerp2_acc_h(acc, g5, m5.y);
        lerp2_acc_h(acc, g6, m6.y); lerp2_acc_h(acc, g7, m7.y);
    }
    // 8-edge window
    for (; e + 6 < cnt; e += 8) {
        int2 m0 = slab[e], m1 = slab[e+2], m2 = slab[e+4], m3 = slab[e+6];
        uint2 g0 = g_y01p[m0.x * 16 + p];
        uint2 g1 = g_y01p[m1.x * 16 + p];
        uint2 g2 = g_y01p[m2.x * 16 + p];
        uint2 g3 = g_y01p[m3.x * 16 + p];
        lerp2_acc_h(acc, g0, m0.y); lerp2_acc_h(acc, g1, m1.y);
        lerp2_acc_h(acc, g2, m2.y); lerp2_acc_h(acc, g3, m3.y);
    }
    for (; e < cnt; e += 2) {
        int2 m = slab[e];
        lerp2_acc_h(acc, g_y01p[m.x * 16 + p], m.y);
    }
    acc.x += __shfl_xor_sync(FULLMASK, acc.x, 16);
    acc.y += __shfl_xor_sync(FULLMASK, acc.y, 16);

    float inv = 1.0f / fmaxf((float)cnt, 1.0f);
    float2 r = *reinterpret_cast<const float2*>(&g_r1[(size_t)w * 32 + 2 * p]);
    float2 b = *reinterpret_cast<const float2*>(&b1[2 * p]);
    float2 h;
    h.x = fmaxf(acc.x * inv + r.x + b.x, 0.0f);
    h.y = fmaxf(acc.y * inv + r.y + b.y, 0.0f);
    if (lane < 16)
        *reinterpret_cast<float2*>(&g_h[(size_t)w * 32 + 2 * p]) = h;
}

// ---------------- layer2 aggregation: warp/node, 8 lanes x 2 feats, 4 edges ----
// fp32 lerp (R14 measured-fast form); fused log_softmax; resets cursor
__global__ __launch_bounds__(256) void edge_agg2(const float* __restrict__ b2,
                                                 float* __restrict__ out) {
    int tid = blockIdx.x * blockDim.x + threadIdx.x;
    int w = tid >> 5;
    int lane = threadIdx.x & 31;
    if (w >= NN) return;
    int cnt = min(g_cur[w], CAP);
    const int2* slab = g_se + (size_t)w * CAP;
    int grp = lane >> 3;         // edge slot mod 4
    int p   = lane & 7;          // feature pair

    float2 acc = make_float2(0.f, 0.f);
    int e = grp;
    // 16-edge window: 4 gathers in flight per lane
    for (; e + 12 < cnt; e += 16) {
        int2 m0 = slab[e], m1 = slab[e+4], m2 = slab[e+8], m3 = slab[e+12];
        uint2 g0 = g_z01p[m0.x * 8 + p];
        uint2 g1 = g_z01p[m1.x * 8 + p];
        uint2 g2 = g_z01p[m2.x * 8 + p];
        uint2 g3 = g_z01p[m3.x * 8 + p];
        lerp2_acc_f(acc, g0, m0.y); lerp2_acc_f(acc, g1, m1.y);
        lerp2_acc_f(acc, g2, m2.y); lerp2_acc_f(acc, g3, m3.y);
    }
    for (; e < cnt; e += 4) {
        int2 m = slab[e];
        lerp2_acc_f(acc, g_z01p[m.x * 8 + p], m.y);
    }
    // combine 4 edge groups
    acc.x += __shfl_xor_sync(FULLMASK, acc.x, 8);
    acc.y += __shfl_xor_sync(FULLMASK, acc.y, 8);
    acc.x += __shfl_xor_sync(FULLMASK, acc.x, 16);
    acc.y += __shfl_xor_sync(FULLMASK, acc.y, 16);

    float inv = 1.0f / fmaxf((float)cnt, 1.0f);
    float2 r = *reinterpret_cast<const float2*>(&g_r2[(size_t)w * 16 + 2 * p]);
    float2 b = *reinterpret_cast<const float2*>(&b2[2 * p]);
    float2 v;
    v.x = acc.x * inv + r.x + b.x;
    v.y = acc.y * inv + r.y + b.y;

    // log_softmax over 16 features (replicated across the 4 groups)
    float m = fmaxf(v.x, v.y);
#pragma unroll
    for (int off = 4; off >= 1; off >>= 1)
        m = fmaxf(m, __shfl_xor_sync(FULLMASK, m, off));
    float s = expf(v.x - m) + expf(v.y - m);
#pragma unroll
    for (int off = 4; off >= 1; off >>= 1)
        s += __shfl_xor_sync(FULLMASK, s, off);
    float lo = logf(s);
    if (lane < 8) {
        float2 o = make_float2(v.x - m - lo, v.y - m - lo);
        *reinterpret_cast<float2*>(&out[(size_t)w * 16 + 2 * p]) = o;
    }
    // reset cursor for the next graph replay (keeps kernel_launch deterministic)
    if (lane == 0) g_cur[w] = 0;
}

// ---------------- launch ----------------
extern "C" void kernel_launch(void* const* d_in, const int* in_sizes, int n_in,
                              void* d_out, int out_size) {
    const float* x   = (const float*)d_in[0];
    const int*   ei  = (const int*)d_in[1];
    const float* ea  = (const float*)d_in[2];
    const float* W1  = (const float*)d_in[3];
    const float* r1w = (const float*)d_in[4];
    const float* b1  = (const float*)d_in[5];
    const float* W2  = (const float*)d_in[6];
    const float* r2w = (const float*)d_in[7];
    const float* b2  = (const float*)d_in[8];
    float* out = (float*)d_out;

    gemm1_scatter<<<GB1 + SB, 256>>>(x, W1, r1w, ei, ea);
    edge_agg1<<<(NN * 32 + 255) / 256, 256>>>(b1);
    gemm2_kernel<<<(NN + 255) / 256, 256>>>(W2, r2w);
    edge_agg2<<<(NN * 32 + 255) / 256, 256>>>(b2, out);
}